// round 3
// baseline (speedup 1.0000x reference)
#include <cuda_runtime.h>
#include <math.h>

#define B_  8
#define L_  2048
#define E_  100
#define FM_ 50
#define Y_  8921
#define K_  9

#define TY  16          // labels per block (attn kernel)
#define LC  256         // l-chunk staged in smem
#define HS_STRIDE 258   // padded row stride for h_s
#define NYT 558         // ceil(Y_/TY)

// scratch (static device arrays are allowed)
__device__ float g_h[(size_t)B_ * L_ * FM_];          // [b][l][f]  3.28 MB
__device__ float g_losspart[B_ * NYT];

// ---- packed f32x2 helpers ------------------------------------------------
__device__ __forceinline__ float2 unpack2(unsigned long long v) {
    float2 f;
    asm("mov.b64 {%0,%1}, %2;" : "=f"(f.x), "=f"(f.y) : "l"(v));
    return f;
}
#define FMA2(d, a, b) \
    asm("fma.rn.f32x2 %0, %1, %2, %0;" : "+l"(d) : "l"(a), "l"(b))

// ---------------------------------------------------------------------------
// Kernel 1: embedding gather + conv1d(K=9, same) + bias + tanh -> g_h[b][l][f]
// ---------------------------------------------------------------------------
__global__ void __launch_bounds__(256) conv_kernel(
    const int* __restrict__ tokens,
    const float* __restrict__ embed_W,
    const float* __restrict__ conv_w,
    const float* __restrict__ conv_b)
{
    __shared__ int   tok_s[72];
    __shared__ float x_s[72][21];          // e-chunk of 20 (pad 21)
    __shared__ float w_s[50][20][9];       // f, e-chunk, k

    const int tid   = threadIdx.x;
    const int b     = blockIdx.y;
    const int lbase = blockIdx.x * 64;

    if (tid < 72) {
        int gl = lbase + tid - 4;
        tok_s[tid] = (gl >= 0 && gl < L_) ? tokens[b * L_ + gl] : -1;
    }
    __syncthreads();

    const int f  = tid >> 2;     // 0..63 (valid < 50)
    const int lg = tid & 3;
    const int l0 = lg * 16;

    float acc[16];
#pragma unroll
    for (int j = 0; j < 16; j++) acc[j] = 0.f;

    for (int ec = 0; ec < 5; ec++) {
        for (int idx = tid; idx < 72 * 20; idx += 256) {
            int i = idx / 20, e = idx % 20;
            int t = tok_s[i];
            x_s[i][e] = (t >= 0) ? embed_W[(size_t)t * E_ + ec * 20 + e] : 0.f;
        }
        for (int idx = tid; idx < 50 * 20 * 9; idx += 256) {
            int ff = idx / 180, r = idx % 180;
            w_s[ff][r / 9][r % 9] = conv_w[ff * (E_ * K_) + ec * 180 + r];
        }
        __syncthreads();

        if (f < FM_) {
            for (int e = 0; e < 20; e++) {
                float xv[24];
#pragma unroll
                for (int t = 0; t < 24; t++) xv[t] = x_s[l0 + t][e];
                float wv[9];
#pragma unroll
                for (int k = 0; k < 9; k++) wv[k] = w_s[f][e][k];
#pragma unroll
                for (int k = 0; k < 9; k++)
#pragma unroll
                    for (int j = 0; j < 16; j++)
                        acc[j] += xv[j + k] * wv[k];
            }
        }
        __syncthreads();
    }

    if (f < FM_) {
        float bias = conv_b[f];
#pragma unroll
        for (int j = 0; j < 16; j++) {
            int l = lbase + l0 + j;
            g_h[((size_t)(b * L_) + l) * FM_ + f] = tanhf(acc[j] + bias);
        }
    }
}

// ---------------------------------------------------------------------------
// Kernel 2: fused label-attention (f32x2 packed FMA, no max-subtraction).
// block = (y-tile of 16, b), 256 threads = 8 warps.
// warp w: label group lg = w&3 (4 labels), position half ph = w>>2 (128 pos).
// Weights pre-duplicated in smem as {u,u,u',u'} float4 (8 float4 per f-row).
// pass1: S,Q via FFMA2; e=exp(s); Z+=e; R+=e*q; raw s persisted in smem.
// pass2: alpha = exp(s)/Z streamed to gmem.
// ---------------------------------------------------------------------------
__global__ void __launch_bounds__(256, 1) attn_kernel(
    const float* __restrict__ U_w,
    const float* __restrict__ final_w,
    const float* __restrict__ final_b,
    const float* __restrict__ target,
    float* __restrict__ out_yhat,
    float* __restrict__ out_alpha,
    int write_alpha)
{
    extern __shared__ float sm[];
    float*  s_smem = sm;                                   // 16*2048 = 32768
    float*  h_s    = s_smem + TY * L_;                     // 50*258  = 12900
    float4* u_d4   = (float4*)(h_s + FM_ * HS_STRIDE);     // 50*8 f4 = 1600 fl
    float4* f_d4   = u_d4 + FM_ * 8;                       // 1600 fl
    float*  iZ_s   = (float*)(f_d4 + FM_ * 8);             // 16
    float*  zr_s   = iZ_s + TY;                            // 64
    float*  loss_s = zr_s + 64;                            // 16

    const int tid  = threadIdx.x;
    const int lane = tid & 31;
    const int warp = tid >> 5;
    const int b    = blockIdx.y;
    const int y0t  = blockIdx.x * TY;

    const int lg  = warp & 3;         // label group -> yl0 = 4*lg
    const int ph  = warp >> 2;        // position half
    const int yl0 = lg * 4;
    const int pbase = ph * 128 + 2 * lane;

    // stage duplicated weights: u_d4[f*8+j] = {u[2j],u[2j],u[2j+1],u[2j+1]}
    for (int idx = tid; idx < FM_ * 8; idx += 256) {
        int f = idx >> 3, j = idx & 7;
        int gy0 = y0t + 2 * j, gy1 = gy0 + 1;
        float u0 = (gy0 < Y_) ? U_w[gy0 * FM_ + f] : 0.f;
        float u1 = (gy1 < Y_) ? U_w[gy1 * FM_ + f] : 0.f;
        u_d4[idx] = make_float4(u0, u0, u1, u1);
        float v0 = (gy0 < Y_) ? final_w[gy0 * FM_ + f] : 0.f;
        float v1 = (gy1 < Y_) ? final_w[gy1 * FM_ + f] : 0.f;
        f_d4[idx] = make_float4(v0, v0, v1, v1);
    }

    float Zacc[4] = {0.f, 0.f, 0.f, 0.f};
    float Racc[4] = {0.f, 0.f, 0.f, 0.f};

    for (int ch = 0; ch < L_ / LC; ch++) {
        const int lb = ch * LC;
        __syncthreads();   // previous chunk readers done (covers dup staging too)
        for (int idx = tid; idx < LC * FM_; idx += 256) {
            int l = idx / FM_, f = idx % FM_;
            h_s[f * HS_STRIDE + l] = g_h[((size_t)(b * L_ + lb + l)) * FM_ + f];
        }
        __syncthreads();

        unsigned long long S[4][2] = {{0ULL,0ULL},{0ULL,0ULL},{0ULL,0ULL},{0ULL,0ULL}};
        unsigned long long Q[4][2] = {{0ULL,0ULL},{0ULL,0ULL},{0ULL,0ULL},{0ULL,0ULL}};

        const float*      hp = h_s + pbase;
        // one f-row = 8 float4 = 8 ulonglong2 entries -> stride 8 per f
        const ulonglong2* up = (const ulonglong2*)(u_d4) + lg * 2;
        const ulonglong2* fp = (const ulonglong2*)(f_d4) + lg * 2;

#pragma unroll 2
        for (int f = 0; f < FM_; f++) {
            unsigned long long h0 = *(const unsigned long long*)(hp);
            unsigned long long h1 = *(const unsigned long long*)(hp + 64);
            ulonglong2 ua = up[0];   // labels yl0, yl0+1 (dup-packed)
            ulonglong2 ub = up[1];   // labels yl0+2, yl0+3
            ulonglong2 fa = fp[0];
            ulonglong2 fb = fp[1];
            FMA2(S[0][0], h0, ua.x); FMA2(S[0][1], h1, ua.x);
            FMA2(S[1][0], h0, ua.y); FMA2(S[1][1], h1, ua.y);
            FMA2(S[2][0], h0, ub.x); FMA2(S[2][1], h1, ub.x);
            FMA2(S[3][0], h0, ub.y); FMA2(S[3][1], h1, ub.y);
            FMA2(Q[0][0], h0, fa.x); FMA2(Q[0][1], h1, fa.x);
            FMA2(Q[1][0], h0, fa.y); FMA2(Q[1][1], h1, fa.y);
            FMA2(Q[2][0], h0, fb.x); FMA2(Q[2][1], h1, fb.x);
            FMA2(Q[3][0], h0, fb.y); FMA2(Q[3][1], h1, fb.y);
            hp += HS_STRIDE; up += 8; fp += 8;
        }

        // epilogue per chunk: exp accumulate + persist raw scores
#pragma unroll
        for (int i = 0; i < 4; i++) {
#pragma unroll
            for (int p = 0; p < 2; p++) {
                float2 s = unpack2(S[i][p]);
                float2 q = unpack2(Q[i][p]);
                float e0 = __expf(s.x), e1 = __expf(s.y);
                Zacc[i] += e0 + e1;
                Racc[i] += e0 * q.x + e1 * q.y;
                *(float2*)(s_smem + (yl0 + i) * L_ + lb + pbase + p * 64) = s;
            }
        }
    }

    // lane reduction of Z,R
#pragma unroll
    for (int o = 16; o > 0; o >>= 1) {
#pragma unroll
        for (int i = 0; i < 4; i++) {
            Zacc[i] += __shfl_xor_sync(0xffffffffu, Zacc[i], o);
            Racc[i] += __shfl_xor_sync(0xffffffffu, Racc[i], o);
        }
    }
    if (lane == 0) {
#pragma unroll
        for (int i = 0; i < 4; i++) {
            zr_s[(warp * 4 + i) * 2 + 0] = Zacc[i];
            zr_s[(warp * 4 + i) * 2 + 1] = Racc[i];
        }
    }
    __syncthreads();

    // finalize per label: combine the two position-half warps
    if (tid < TY) {
        int y = tid;
        int g = y >> 2, i = y & 3;
        float Z = zr_s[(g * 4 + i) * 2 + 0] + zr_s[((g + 4) * 4 + i) * 2 + 0];
        float R = zr_s[(g * 4 + i) * 2 + 1] + zr_s[((g + 4) * 4 + i) * 2 + 1];
        iZ_s[y] = 1.f / Z;
        float lossterm = 0.f;
        int gy = y0t + y;
        if (gy < Y_) {
            float r  = R / Z + final_b[gy];
            float yh = 1.f / (1.f + expf(-r));
            out_yhat[b * Y_ + gy] = yh;
            float t = target[b * Y_ + gy];
            lossterm = t * logf(yh + 1e-12f) + (1.f - t) * logf(1.f - yh + 1e-12f);
        }
        loss_s[y] = lossterm;
    }
    __syncthreads();
    if (tid == 0) {
        float s = 0.f;
#pragma unroll
        for (int i = 0; i < TY; i++) s += loss_s[i];
        g_losspart[b * gridDim.x + blockIdx.x] = s;
    }

    // pass 2: alpha = exp(s) / Z
    if (write_alpha) {
#pragma unroll
        for (int i = 0; i < 4; i++) {
            int gy = y0t + yl0 + i;
            if (gy >= Y_) continue;
            float iZ = iZ_s[yl0 + i];
            float*       ap = out_alpha + ((size_t)b * Y_ + gy) * L_ + ph * 1024;
            const float* sp = s_smem + (yl0 + i) * L_ + ph * 1024;
#pragma unroll 4
            for (int l = lane; l < 1024; l += 32)
                ap[l] = __expf(sp[l]) * iZ;
        }
    }
}

// ---------------------------------------------------------------------------
// Kernel 3: deterministic loss reduction
// ---------------------------------------------------------------------------
__global__ void loss_kernel(float* __restrict__ out_loss, int npart)
{
    __shared__ float red[256];
    float s = 0.f;
    for (int i = threadIdx.x; i < npart; i += 256) s += g_losspart[i];
    red[threadIdx.x] = s;
    __syncthreads();
    for (int o = 128; o > 0; o >>= 1) {
        if (threadIdx.x < o) red[threadIdx.x] += red[threadIdx.x + o];
        __syncthreads();
    }
    if (threadIdx.x == 0) *out_loss = -red[0] / (float)(B_ * Y_);
}

// ---------------------------------------------------------------------------
extern "C" void kernel_launch(void* const* d_in, const int* in_sizes, int n_in,
                              void* d_out, int out_size)
{
    const int*   tokens  = (const int*)  d_in[0];
    const float* target  = (const float*)d_in[1];
    const float* embed_W = (const float*)d_in[2];
    const float* conv_w  = (const float*)d_in[3];
    const float* conv_b  = (const float*)d_in[4];
    const float* U_w     = (const float*)d_in[5];
    const float* final_w = (const float*)d_in[6];
    const float* final_b = (const float*)d_in[7];
    float* out = (float*)d_out;

    const long long yhat_n  = (long long)B_ * Y_;                 // 71368
    const long long total_n = yhat_n + 1 + (long long)B_ * Y_ * L_;
    int write_loss  = (out_size >= (int)(yhat_n + 1)) ? 1 : 0;
    int write_alpha = ((long long)out_size >= total_n) ? 1 : 0;

    const int smem_bytes =
        (TY * L_ + FM_ * HS_STRIDE + 2 * (FM_ * 8 * 4) + TY + 64 + TY) * 4;
    cudaFuncSetAttribute(attn_kernel, cudaFuncAttributeMaxDynamicSharedMemorySize,
                         smem_bytes);

    conv_kernel<<<dim3(L_ / 64, B_), 256>>>(tokens, embed_W, conv_w, conv_b);

    float* out_alpha = out + yhat_n + 1;
    attn_kernel<<<dim3(NYT, B_), 256, smem_bytes>>>(
        U_w, final_w, final_b, target, out, out_alpha, write_alpha);

    if (write_loss)
        loss_kernel<<<1, 256>>>(out + yhat_n, B_ * NYT);
}

// round 5
// speedup vs baseline: 2.1748x; 2.1748x over previous
#include <cuda_runtime.h>
#include <math.h>

#define B_  8
#define L_  2048
#define E_  100
#define FM_ 50
#define Y_  8921
#define K_  9

#define TY  16          // labels per block (attn kernel)
#define LC  256         // l-chunk staged in smem
#define NYT 558         // ceil(Y_/TY)

// scratch (static device arrays are allowed)
__device__ float g_h[(size_t)B_ * FM_ * L_];          // [b][f][l]  3.28 MB
__device__ float g_losspart[B_ * NYT];

// ---- packed f32x2 helpers ------------------------------------------------
__device__ __forceinline__ float2 unpack2(unsigned long long v) {
    float2 f;
    asm("mov.b64 {%0,%1}, %2;" : "=f"(f.x), "=f"(f.y) : "l"(v));
    return f;
}
#define FMA2(d, a, b) \
    asm("fma.rn.f32x2 %0, %1, %2, %0;" : "+l"(d) : "l"(a), "l"(b))

// ---------------------------------------------------------------------------
// Kernel 1: embedding gather + conv1d(K=9, same) + bias + tanh -> g_h[b][f][l]
// ---------------------------------------------------------------------------
__global__ void __launch_bounds__(256) conv_kernel(
    const int* __restrict__ tokens,
    const float* __restrict__ embed_W,
    const float* __restrict__ conv_w,
    const float* __restrict__ conv_b)
{
    __shared__ int   tok_s[72];
    __shared__ float x_s[72][21];          // e-chunk of 20 (pad 21)
    __shared__ float w_s[50][20][9];       // f, e-chunk, k

    const int tid   = threadIdx.x;
    const int b     = blockIdx.y;
    const int lbase = blockIdx.x * 64;

    if (tid < 72) {
        int gl = lbase + tid - 4;
        tok_s[tid] = (gl >= 0 && gl < L_) ? tokens[b * L_ + gl] : -1;
    }
    __syncthreads();

    const int f  = tid >> 2;     // 0..63 (valid < 50)
    const int lg = tid & 3;
    const int l0 = lg * 16;

    float acc[16];
#pragma unroll
    for (int j = 0; j < 16; j++) acc[j] = 0.f;

    for (int ec = 0; ec < 5; ec++) {
        for (int idx = tid; idx < 72 * 20; idx += 256) {
            int i = idx / 20, e = idx % 20;
            int t = tok_s[i];
            x_s[i][e] = (t >= 0) ? embed_W[(size_t)t * E_ + ec * 20 + e] : 0.f;
        }
        for (int idx = tid; idx < 50 * 20 * 9; idx += 256) {
            int ff = idx / 180, r = idx % 180;
            w_s[ff][r / 9][r % 9] = conv_w[ff * (E_ * K_) + ec * 180 + r];
        }
        __syncthreads();

        if (f < FM_) {
            for (int e = 0; e < 20; e++) {
                float xv[24];
#pragma unroll
                for (int t = 0; t < 24; t++) xv[t] = x_s[l0 + t][e];
                float wv[9];
#pragma unroll
                for (int k = 0; k < 9; k++) wv[k] = w_s[f][e][k];
#pragma unroll
                for (int k = 0; k < 9; k++)
#pragma unroll
                    for (int j = 0; j < 16; j++)
                        acc[j] += xv[j + k] * wv[k];
            }
        }
        __syncthreads();
    }

    if (f < FM_) {
        float bias = conv_b[f];
#pragma unroll
        for (int j = 0; j < 16; j++) {
            int l = lbase + l0 + j;
            g_h[((size_t)(b * FM_) + f) * L_ + l] = tanhf(acc[j] + bias);
        }
    }
}

// ---------------------------------------------------------------------------
// Kernel 2: fused label-attention, low-smem / high-occupancy variant.
// block = (y-tile of 16, b), 256 threads = 8 warps (3 CTAs/SM).
// warp w: label group lg = w&3 (4 labels), position half ph = w>>2 (128 pos).
// pass1: S,Q via FFMA2; e=exp(s) streamed to alpha gmem (SCALAR stores —
//        the alpha region is only 4-byte aligned!); Z+=e; R+=e*q.
// tail:  iZ per label; block re-reads its own alpha (L2-hot) and scales
//        in place with scalar accesses.
// ---------------------------------------------------------------------------
__global__ void __launch_bounds__(256, 3) attn_kernel(
    const float* __restrict__ U_w,
    const float* __restrict__ final_w,
    const float* __restrict__ final_b,
    const float* __restrict__ target,
    float* __restrict__ out_yhat,
    float* __restrict__ out_alpha,
    int write_alpha)
{
    __shared__ float  h_s[FM_ * LC];        // 51.2 KB, row stride 256 (f<<8)
    __shared__ float4 u_d4[FM_ * 8];        // dup-packed U:    6.4 KB
    __shared__ float4 f_d4[FM_ * 8];        // dup-packed final 6.4 KB
    __shared__ float  zr_s[64];
    __shared__ float  iZ_s[TY];
    __shared__ float  loss_s[TY];

    const int tid  = threadIdx.x;
    const int lane = tid & 31;
    const int warp = tid >> 5;
    const int b    = blockIdx.y;
    const int y0t  = blockIdx.x * TY;

    const int lg  = warp & 3;         // label group -> yl0 = 4*lg
    const int ph  = warp >> 2;        // position half (0/1)
    const int yl0 = lg * 4;
    const int pbase = ph * 128 + 2 * lane;

    // stage duplicated weights: u_d4[f*8+j] = {u[2j],u[2j],u[2j+1],u[2j+1]}
    for (int idx = tid; idx < FM_ * 8; idx += 256) {
        int f = idx >> 3, j = idx & 7;
        int gy0 = y0t + 2 * j, gy1 = gy0 + 1;
        float u0 = (gy0 < Y_) ? U_w[gy0 * FM_ + f] : 0.f;
        float u1 = (gy1 < Y_) ? U_w[gy1 * FM_ + f] : 0.f;
        u_d4[idx] = make_float4(u0, u0, u1, u1);
        float v0 = (gy0 < Y_) ? final_w[gy0 * FM_ + f] : 0.f;
        float v1 = (gy1 < Y_) ? final_w[gy1 * FM_ + f] : 0.f;
        f_d4[idx] = make_float4(v0, v0, v1, v1);
    }

    float Zacc[4] = {0.f, 0.f, 0.f, 0.f};
    float Racc[4] = {0.f, 0.f, 0.f, 0.f};

    const size_t arow = (size_t)b * Y_ + y0t;   // first label row of this block

    for (int ch = 0; ch < L_ / LC; ch++) {
        const int lb = ch * LC;
        __syncthreads();   // previous chunk readers done (covers weight staging)
        // stage h chunk: g_h[b][f][lb..lb+255]  (float4, fully coalesced;
        // g_h is a __device__ array -> 16B aligned, safe)
        {
            const float4* gsrc =
                (const float4*)(g_h + (size_t)b * FM_ * L_ + lb);
            float4* dst = (float4*)h_s;
            for (int idx = tid; idx < FM_ * LC / 4; idx += 256) {
                int f = idx >> 6, v = idx & 63;       // 64 float4 per f-row
                dst[(f << 6) + v] = gsrc[(size_t)f * (L_ / 4) + v];
            }
        }
        __syncthreads();

        unsigned long long S[4][2] = {{0,0},{0,0},{0,0},{0,0}};
        unsigned long long Q[4][2] = {{0,0},{0,0},{0,0},{0,0}};

        const float*      hp = h_s + pbase;
        const ulonglong2* up = (const ulonglong2*)(u_d4) + lg * 2;
        const ulonglong2* fp = (const ulonglong2*)(f_d4) + lg * 2;

#pragma unroll 2
        for (int f = 0; f < FM_; f++) {
            unsigned long long h0 = *(const unsigned long long*)(hp);
            unsigned long long h1 = *(const unsigned long long*)(hp + 64);
            ulonglong2 ua = up[0];   // labels yl0, yl0+1 (dup-packed)
            ulonglong2 ub = up[1];   // labels yl0+2, yl0+3
            ulonglong2 fa = fp[0];
            ulonglong2 fb = fp[1];
            FMA2(S[0][0], h0, ua.x); FMA2(S[0][1], h1, ua.x);
            FMA2(S[1][0], h0, ua.y); FMA2(S[1][1], h1, ua.y);
            FMA2(S[2][0], h0, ub.x); FMA2(S[2][1], h1, ub.x);
            FMA2(S[3][0], h0, ub.y); FMA2(S[3][1], h1, ub.y);
            FMA2(Q[0][0], h0, fa.x); FMA2(Q[0][1], h1, fa.x);
            FMA2(Q[1][0], h0, fa.y); FMA2(Q[1][1], h1, fa.y);
            FMA2(Q[2][0], h0, fb.x); FMA2(Q[2][1], h1, fb.x);
            FMA2(Q[3][0], h0, fb.y); FMA2(Q[3][1], h1, fb.y);
            hp += LC; up += 8; fp += 8;
        }

        // per-chunk epilogue: e = exp(s) -> gmem (unnormalized, SCALAR stores)
#pragma unroll
        for (int i = 0; i < 4; i++) {
            const int gy = y0t + yl0 + i;
            float* abase = out_alpha + (arow + yl0 + i) * L_ + lb + pbase;
#pragma unroll
            for (int p = 0; p < 2; p++) {
                float2 s = unpack2(S[i][p]);
                float2 q = unpack2(Q[i][p]);
                float e0 = __expf(s.x), e1 = __expf(s.y);
                Zacc[i] += e0 + e1;
                Racc[i] += e0 * q.x + e1 * q.y;
                if (write_alpha && gy < Y_) {
                    abase[p * 64 + 0] = e0;
                    abase[p * 64 + 1] = e1;
                }
            }
        }
    }

    // lane reduction of Z,R
#pragma unroll
    for (int o = 16; o > 0; o >>= 1) {
#pragma unroll
        for (int i = 0; i < 4; i++) {
            Zacc[i] += __shfl_xor_sync(0xffffffffu, Zacc[i], o);
            Racc[i] += __shfl_xor_sync(0xffffffffu, Racc[i], o);
        }
    }
    if (lane == 0) {
#pragma unroll
        for (int i = 0; i < 4; i++) {
            zr_s[(warp * 4 + i) * 2 + 0] = Zacc[i];
            zr_s[(warp * 4 + i) * 2 + 1] = Racc[i];
        }
    }
    __syncthreads();

    // finalize per label: combine the two position-half warps
    if (tid < TY) {
        int y = tid;
        int g = y >> 2, i = y & 3;
        float Z = zr_s[(g * 4 + i) * 2 + 0] + zr_s[((g + 4) * 4 + i) * 2 + 0];
        float R = zr_s[(g * 4 + i) * 2 + 1] + zr_s[((g + 4) * 4 + i) * 2 + 1];
        iZ_s[y] = 1.f / Z;
        float lossterm = 0.f;
        int gy = y0t + y;
        if (gy < Y_) {
            float r  = R / Z + final_b[gy];
            float yh = 1.f / (1.f + expf(-r));
            out_yhat[b * Y_ + gy] = yh;
            float t = target[b * Y_ + gy];
            lossterm = t * logf(yh + 1e-12f) + (1.f - t) * logf(1.f - yh + 1e-12f);
        }
        loss_s[y] = lossterm;
    }
    __syncthreads();
    if (tid == 0) {
        float s = 0.f;
#pragma unroll
        for (int i = 0; i < TY; i++) s += loss_s[i];
        g_losspart[b * gridDim.x + blockIdx.x] = s;
    }

    // in-place rescale: block's alpha rows are still L2-hot. SCALAR accesses
    // (alpha region is only 4-byte aligned).
    if (write_alpha) {
#pragma unroll 1
        for (int y = 0; y < TY; y++) {
            int gy = y0t + y;
            if (gy >= Y_) break;
            float iZ = iZ_s[y];
            float* ap = out_alpha + (arow + y) * L_;
#pragma unroll 4
            for (int v = tid; v < L_; v += 256)
                ap[v] *= iZ;
        }
    }
}

// ---------------------------------------------------------------------------
// Kernel 3: deterministic loss reduction
// ---------------------------------------------------------------------------
__global__ void loss_kernel(float* __restrict__ out_loss, int npart)
{
    __shared__ float red[256];
    float s = 0.f;
    for (int i = threadIdx.x; i < npart; i += 256) s += g_losspart[i];
    red[threadIdx.x] = s;
    __syncthreads();
    for (int o = 128; o > 0; o >>= 1) {
        if (threadIdx.x < o) red[threadIdx.x] += red[threadIdx.x + o];
        __syncthreads();
    }
    if (threadIdx.x == 0) *out_loss = -red[0] / (float)(B_ * Y_);
}

// ---------------------------------------------------------------------------
extern "C" void kernel_launch(void* const* d_in, const int* in_sizes, int n_in,
                              void* d_out, int out_size)
{
    const int*   tokens  = (const int*)  d_in[0];
    const float* target  = (const float*)d_in[1];
    const float* embed_W = (const float*)d_in[2];
    const float* conv_w  = (const float*)d_in[3];
    const float* conv_b  = (const float*)d_in[4];
    const float* U_w     = (const float*)d_in[5];
    const float* final_w = (const float*)d_in[6];
    const float* final_b = (const float*)d_in[7];
    float* out = (float*)d_out;

    const long long yhat_n  = (long long)B_ * Y_;                 // 71368
    const long long total_n = yhat_n + 1 + (long long)B_ * Y_ * L_;
    int write_loss  = (out_size >= (int)(yhat_n + 1)) ? 1 : 0;
    int write_alpha = ((long long)out_size >= total_n) ? 1 : 0;

    conv_kernel<<<dim3(L_ / 64, B_), 256>>>(tokens, embed_W, conv_w, conv_b);

    float* out_alpha = out + yhat_n + 1;
    attn_kernel<<<dim3(NYT, B_), 256>>>(
        U_w, final_w, final_b, target, out, out_alpha, write_alpha);

    if (write_loss)
        loss_kernel<<<1, 256>>>(out + yhat_n, B_ * NYT);
}